// round 8
// baseline (speedup 1.0000x reference)
#include <cuda_runtime.h>
#include <cstdint>

// Integer-exact fused QAT conv stack (bit-exact vs fp32 reference).
// Persistent blocks + cp.async.bulk 3-deep ring of x tiles in smem.
// Sized for 4 blocks/SM: TILE=1024, PP=4, STAGES=3, regs<=64.

#define NT     256
#define PP     4
#define TILE   (NT * PP)          // 1024 positions
#define HALO   8
#define ROWF   (TILE + 2 * HALO)  // 1040 floats per channel row
#define STAGES 3
#define BATCH  16

__device__ __forceinline__ int cvtrd(float v) {
    return __float2int_rd(fmaf(v, 128.0f, 0.5f));   // floor(v*128 + 0.5)
}
__device__ __forceinline__ int packsat2(int a, int b, int c) {
    int d;
    asm("cvt.pack.sat.s8.s32.b32 %0, %1, %2, %3;"
        : "=r"(d) : "r"(a), "r"(b), "r"(c));
    return d;
}
// bytes [v0,v1,v2,v3]; same helper for weights and data -> dp4a order-invariant
__device__ __forceinline__ int pack4sat(int v0, int v1, int v2, int v3) {
    return packsat2(v1, v0, packsat2(v3, v2, 0));
}
__device__ __forceinline__ int qpack(float a, float b, float c, float d) {
    return pack4sat(cvtrd(a), cvtrd(b), cvtrd(c), cvtrd(d));
}

__device__ __forceinline__ uint32_t s2u(const void* p) {
    uint32_t a;
    asm("{ .reg .u64 t; cvta.to.shared.u64 t, %1; cvt.u32.u64 %0, t; }"
        : "=r"(a) : "l"(p));
    return a;
}
__device__ __forceinline__ void mbar_init(uint32_t a, uint32_t cnt) {
    asm volatile("mbarrier.init.shared.b64 [%0], %1;" :: "r"(a), "r"(cnt) : "memory");
}
__device__ __forceinline__ void mbar_arrive(uint32_t a) {
    asm volatile("mbarrier.arrive.shared.b64 _, [%0];" :: "r"(a) : "memory");
}
__device__ __forceinline__ void mbar_expect(uint32_t a, uint32_t bytes) {
    asm volatile("mbarrier.arrive.expect_tx.shared.b64 _, [%0], %1;"
                 :: "r"(a), "r"(bytes) : "memory");
}
__device__ __forceinline__ void mbar_wait_acq(uint32_t a, int par) {
    asm volatile(
        "{\n\t.reg .pred P;\n"
        "W_%=:\n\t"
        "mbarrier.try_wait.parity.acquire.cta.shared::cta.b64 P, [%0], %1, 0x989680;\n\t"
        "@P bra D_%=;\n\t"
        "bra W_%=;\n"
        "D_%=:\n\t}"
        :: "r"(a), "r"(par) : "memory");
}
__device__ __forceinline__ void mbar_wait_rlx(uint32_t a, int par) {
    asm volatile(
        "{\n\t.reg .pred P;\n"
        "W_%=:\n\t"
        "mbarrier.try_wait.parity.relaxed.cta.shared::cta.b64 P, [%0], %1, 0x989680;\n\t"
        "@P bra D_%=;\n\t"
        "bra W_%=;\n"
        "D_%=:\n\t}"
        :: "r"(a), "r"(par) : "memory");
}
__device__ __forceinline__ void bulk_g2s(uint32_t dst, const void* src,
                                         uint32_t bytes, uint32_t mbar) {
    asm volatile(
        "cp.async.bulk.shared::cta.global.mbarrier::complete_tx::bytes "
        "[%0], [%1], %2, [%3];"
        :: "r"(dst), "l"(src), "r"(bytes), "r"(mbar) : "memory");
}

// wall layout: [0..23] w1 packed (oc*3+k), [24..31] 128*b1+64,
//              [32..43] w2 packed (oc*6+k*2+h), [44..45] 128*b2+64
template <bool GUARD>
__device__ __forceinline__ void tail_compute(
    const int* xw, const int* wall, int base, int L, float* ob)
{
    int yl[PP + 2], yh[PP + 2];
#pragma unroll
    for (int i = 0; i < PP + 2; i++) {
        int x0 = xw[i], x1 = xw[i + 1], x2 = xw[i + 2];
        int yv[8];
#pragma unroll
        for (int oc = 0; oc < 8; oc++) {
            int acc = __dp4a(x0, wall[oc * 3 + 0], wall[24 + oc]);
            acc     = __dp4a(x1, wall[oc * 3 + 1], acc);
            acc     = __dp4a(x2, wall[oc * 3 + 2], acc);
            yv[oc]  = acc >> 7;
        }
        int lo = pack4sat(yv[0], yv[1], yv[2], yv[3]);
        int hi = pack4sat(yv[4], yv[5], yv[6], yv[7]);
        if (GUARD) {
            int q = base - 1 + i;
            bool valid = (q >= 0) && (q < L);
            lo = valid ? lo : 0;
            hi = valid ? hi : 0;
        }
        yl[i] = lo; yh[i] = hi;
    }

    float f0[PP], f1[PP];
#pragma unroll
    for (int p = 0; p < PP; p++) {
        int a0 = __dp4a(yl[p],     wall[32], wall[44]);
        a0     = __dp4a(yh[p],     wall[33], a0);
        a0     = __dp4a(yl[p + 1], wall[34], a0);
        a0     = __dp4a(yh[p + 1], wall[35], a0);
        a0     = __dp4a(yl[p + 2], wall[36], a0);
        a0     = __dp4a(yh[p + 2], wall[37], a0);
        int a1 = __dp4a(yl[p],     wall[38], wall[45]);
        a1     = __dp4a(yh[p],     wall[39], a1);
        a1     = __dp4a(yl[p + 1], wall[40], a1);
        a1     = __dp4a(yh[p + 1], wall[41], a1);
        a1     = __dp4a(yl[p + 2], wall[42], a1);
        a1     = __dp4a(yh[p + 2], wall[43], a1);
        f0[p] = (float)min(max(a0 >> 7, -128), 127) * 0.0078125f;
        f1[p] = (float)min(max(a1 >> 7, -128), 127) * 0.0078125f;
    }
    *(float4*)(ob + base)             = make_float4(f0[0], f0[1], f0[2], f0[3]);
    *(float4*)(ob + (size_t)L + base) = make_float4(f1[0], f1[1], f1[2], f1[3]);
}

__global__ __launch_bounds__(NT, 4) void fused_qconv_pipe3(
    const float* __restrict__ x,
    const float* __restrict__ w1, const float* __restrict__ b1,
    const float* __restrict__ gamma, const float* __restrict__ beta,
    const float* __restrict__ bn_mean, const float* __restrict__ bn_var,
    const float* __restrict__ w2, const float* __restrict__ b2,
    float* __restrict__ out, int L)
{
    extern __shared__ float dsm[];            // [STAGES][4][ROWF]
    __shared__ __align__(8) uint64_t mbar[2 * STAGES];  // full[s], empty[s]
    __shared__ int wall[48];
    const int tid = threadIdx.x;

    // ---- weight prep ----
    if (tid < 24) {
        int oc = tid / 3, k = tid % 3;
        float sf = (float)((double)gamma[oc] / sqrt((double)bn_var[oc] + 1e-5));
        const float* wb = w1 + oc * 12 + k;
        wall[tid] = qpack(wb[0] * sf, wb[3] * sf, wb[6] * sf, wb[9] * sf);
    } else if (tid < 32) {
        int oc = tid - 24;
        float sf = (float)((double)gamma[oc] / sqrt((double)bn_var[oc] + 1e-5));
        int bi = min(max(cvtrd((b1[oc] - bn_mean[oc]) * sf + beta[oc]), -128), 127);
        wall[tid] = bi * 128 + 64;
    } else if (tid < 44) {
        int t = tid - 32, oc = t / 6, r = t % 6, k = r >> 1, h = r & 1;
        const float* wb = w2 + oc * 24 + h * 12 + k;
        wall[tid] = qpack(wb[0], wb[3], wb[6], wb[9]);
    } else if (tid < 46) {
        wall[tid] = min(max(cvtrd(b2[tid - 44]), -128), 127) * 128 + 64;
    }

    uint32_t fullb[STAGES], emptyb[STAGES];
#pragma unroll
    for (int s = 0; s < STAGES; s++) {
        fullb[s]  = s2u(&mbar[s]);
        emptyb[s] = s2u(&mbar[STAGES + s]);
    }
    if (tid == 0) {
#pragma unroll
        for (int s = 0; s < STAGES; s++) {
            mbar_init(fullb[s], 1);      // completes via expect_tx + tx bytes
            mbar_init(emptyb[s], NT);    // all threads arrive after consuming
        }
    }
    __syncthreads();

    const int tpr    = L / TILE;          // tiles per batch row (512)
    const int ntiles = BATCH * tpr;       // 8192
    const int G      = gridDim.x;
    const int bid    = blockIdx.x;
    const int n_my   = (bid < ntiles) ? (ntiles - bid + G - 1) / G : 0;

    uint32_t stage_addr[STAGES];
#pragma unroll
    for (int s = 0; s < STAGES; s++) stage_addr[s] = s2u(dsm + s * 4 * ROWF);

    // producer: issue this block's i-th tile into ring slot
    auto issue = [&](int i, int slot) {
        int t  = bid + i * G;
        int bb = t / tpr, tr = t - bb * tpr;
        int ts = tr * TILE;
        int start = ts - HALO; if (start < 0) start = 0;
        int end   = ts + TILE + HALO; if (end > L) end = L;
        uint32_t nb = (uint32_t)(end - start) * 4u;
        uint32_t dst_off = (uint32_t)(start - (ts - HALO)) * 4u;
        const float* xb = x + (size_t)bb * 4 * L;
        mbar_expect(fullb[slot], nb * 4u);
#pragma unroll
        for (int c = 0; c < 4; c++)
            bulk_g2s(stage_addr[slot] + c * (ROWF * 4) + dst_off,
                     xb + (size_t)c * L + start, nb, fullb[slot]);
    };

    if (tid == 0) {    // prologue fills the ring
        if (n_my > 0) issue(0, 0);
        if (n_my > 1) issue(1, 1);
        if (n_my > 2) issue(2, 2);
    }

    int cs = 0, cp = 0;   // consumer cursor (stage, phase)
    for (int i = 0; i < n_my; i++) {
        int t  = bid + i * G;
        int bb = t / tpr, tr = t - bb * tpr;
        int ts = tr * TILE;
        bool edge = (tr == 0) || (tr == tpr - 1);

        mbar_wait_acq(fullb[cs], cp);

        float* xs = dsm + cs * 4 * ROWF;
        if (edge) {
            if (tid < 32) {     // zero-fill out-of-range halo words
                int c = tid >> 3, o = tid & 7;
                if (tr == 0)       xs[c * ROWF + o] = 0.0f;
                if (tr == tpr - 1) xs[c * ROWF + (ROWF - 8) + o] = 0.0f;
            }
            __syncthreads();
        }

        const int base = ts + tid * PP;
        const float* r0 = xs + 0 * ROWF + tid * PP + (HALO - 4);
        const float* r1 = xs + 1 * ROWF + tid * PP + (HALO - 4);
        const float* r2 = xs + 2 * ROWF + tid * PP + (HALO - 4);
        const float* r3 = xs + 3 * ROWF + tid * PP + (HALO - 4);

        // 3 float4 per channel cover positions base-4 .. base+7
        float4 a0 = *(const float4*)(r0 + 0);
        float4 a1 = *(const float4*)(r0 + 4);
        float4 a2 = *(const float4*)(r0 + 8);
        float4 b0 = *(const float4*)(r1 + 0);
        float4 b1v = *(const float4*)(r1 + 4);
        float4 b2v = *(const float4*)(r1 + 8);
        float4 c0 = *(const float4*)(r2 + 0);
        float4 c1 = *(const float4*)(r2 + 4);
        float4 c2 = *(const float4*)(r2 + 8);
        float4 d0 = *(const float4*)(r3 + 0);
        float4 d1 = *(const float4*)(r3 + 4);
        float4 d2 = *(const float4*)(r3 + 8);

        int xw[PP + 4];   // xw[j] = packed fq(x) at position base-2+j
        xw[0] = qpack(a0.z, b0.z,  c0.z, d0.z);
        xw[1] = qpack(a0.w, b0.w,  c0.w, d0.w);
        xw[2] = qpack(a1.x, b1v.x, c1.x, d1.x);
        xw[3] = qpack(a1.y, b1v.y, c1.y, d1.y);
        xw[4] = qpack(a1.z, b1v.z, c1.z, d1.z);
        xw[5] = qpack(a1.w, b1v.w, c1.w, d1.w);
        xw[6] = qpack(a2.x, b2v.x, c2.x, d2.x);
        xw[7] = qpack(a2.y, b2v.y, c2.y, d2.y);

        float* ob = out + (size_t)bb * 2 * L;
        if (edge) tail_compute<true >(xw, wall, base, L, ob);
        else      tail_compute<false>(xw, wall, base, L, ob);

        mbar_arrive(emptyb[cs]);      // release this slot

        if (tid == 0 && i + STAGES < n_my) {
            mbar_wait_rlx(emptyb[cs], cp);   // post-wait access is async-proxy only
            issue(i + STAGES, cs);
        }

        if (++cs == STAGES) { cs = 0; cp ^= 1; }
    }
}

extern "C" void kernel_launch(void* const* d_in, const int* in_sizes, int n_in,
                              void* d_out, int out_size)
{
    const float* x       = (const float*)d_in[0];
    const float* w1      = (const float*)d_in[1];
    const float* b1      = (const float*)d_in[2];
    const float* gamma   = (const float*)d_in[3];
    const float* beta    = (const float*)d_in[4];
    const float* bn_mean = (const float*)d_in[5];
    const float* bn_var  = (const float*)d_in[6];
    const float* w2      = (const float*)d_in[7];
    const float* b2      = (const float*)d_in[8];
    float* out = (float*)d_out;

    const int B = 16;
    const int L = in_sizes[0] / (B * 4);

    const int smem_bytes = STAGES * 4 * ROWF * (int)sizeof(float);  // 49920
    cudaFuncSetAttribute(fused_qconv_pipe3,
                         cudaFuncAttributeMaxDynamicSharedMemorySize, smem_bytes);

    const int grid = 148 * 4;   // persistent, 4 blocks/SM
    fused_qconv_pipe3<<<grid, NT, smem_bytes>>>(
        x, w1, b1, gamma, beta, bn_mean, bn_var, w2, b2, out, L);
}

// round 9
// speedup vs baseline: 1.2760x; 1.2760x over previous
#include <cuda_runtime.h>

// Integer-exact fused QAT conv stack (bit-exact vs fp32 reference).
// 3-stage smem design (R3) resized for occupancy: TL=2048 -> 24.6KB smem,
// __launch_bounds__(256,6) -> <=42 regs, ~6-8 blocks/SM.

#define TL 2048      // tile positions per block
#define NT 256       // threads per block

__device__ __forceinline__ int cvtrd(float v) {
    return __float2int_rd(fmaf(v, 128.0f, 0.5f));   // floor(v*128 + 0.5)
}
__device__ __forceinline__ int packsat2(int a, int b, int c) {
    int d;
    asm("cvt.pack.sat.s8.s32.b32 %0, %1, %2, %3;"
        : "=r"(d) : "r"(a), "r"(b), "r"(c));
    return d;
}
// bytes perm of [v0..v3]; same helper for weights and data -> dp4a invariant
__device__ __forceinline__ int pack4sat(int v0, int v1, int v2, int v3) {
    return packsat2(v1, v0, packsat2(v3, v2, 0));
}
__device__ __forceinline__ int qpack(float a, float b, float c, float d) {
    return pack4sat(cvtrd(a), cvtrd(b), cvtrd(c), cvtrd(d));
}

__global__ __launch_bounds__(NT, 6) void fused_qconv_i8o(
    const float* __restrict__ x,
    const float* __restrict__ w1, const float* __restrict__ b1,
    const float* __restrict__ gamma, const float* __restrict__ beta,
    const float* __restrict__ bn_mean, const float* __restrict__ bn_var,
    const float* __restrict__ w2, const float* __restrict__ b2,
    float* __restrict__ out, int L)
{
    __shared__ int w1p[8][3];        // conv1 w: 4 in-ch packed per (oc,k)
    __shared__ int bo1[8];           // 128*b1_int + 64
    __shared__ int w2p[2][3][2];     // conv2 w: [oc][k][half]
    __shared__ int bo2[2];           // 128*b2_int + 64
    extern __shared__ int smem[];
    int* xs  = smem;                 // [TL+8]  packed x, xs[i] = pos ts-4+i
    int* ysL = smem + (TL + 8);      // [TL+4]  y ch0..3, ysL[i] = pos ts-2+i
    int* ysH = ysL + (TL + 4);       // [TL+4]  y ch4..7

    const int tid = threadIdx.x;
    const int bb  = blockIdx.y;
    const int ts  = blockIdx.x * TL;
    const float* xb = x + (size_t)bb * 4 * L;
    const bool edge = (blockIdx.x == 0) | (blockIdx.x == gridDim.x - 1);

    // ---- halos + tiny weight set (disjoint tid ranges) ----
    if (tid < 4) {                                // left halo: pos ts-4+tid
        int p = ts - 4 + tid, w = 0;
        if (p >= 0)
            w = qpack(xb[p], xb[(size_t)L + p],
                      xb[(size_t)2*L + p], xb[(size_t)3*L + p]);
        xs[tid] = w;
    } else if (tid < 8) {                         // right halo
        int p = ts + TL + (tid - 4), w = 0;
        if (p < L)
            w = qpack(xb[p], xb[(size_t)L + p],
                      xb[(size_t)2*L + p], xb[(size_t)3*L + p]);
        xs[TL + 4 + (tid - 4)] = w;
    } else if (tid >= 32 && tid < 56) {           // w1 packed
        int t = tid - 32, oc = t / 3, k = t % 3;
        float sf = (float)((double)gamma[oc] / sqrt((double)bn_var[oc] + 1e-5));
        const float* wb = w1 + oc * 12 + k;
        w1p[oc][k] = qpack(wb[0] * sf, wb[3] * sf, wb[6] * sf, wb[9] * sf);
    } else if (tid >= 56 && tid < 64) {           // folded bias 1
        int oc = tid - 56;
        float sf = (float)((double)gamma[oc] / sqrt((double)bn_var[oc] + 1e-5));
        int bi = min(max(cvtrd((b1[oc] - bn_mean[oc]) * sf + beta[oc]), -128), 127);
        bo1[oc] = bi * 128 + 64;
    } else if (tid >= 64 && tid < 76) {           // w2 packed
        int t = tid - 64, oc = t / 6, r = t % 6, k = r >> 1, h = r & 1;
        const float* wb = w2 + oc * 24 + h * 12 + k;
        w2p[oc][k][h] = qpack(wb[0], wb[3], wb[6], wb[9]);
    } else if (tid >= 76 && tid < 78) {           // bias 2
        int oc = tid - 76;
        bo2[oc] = min(max(cvtrd(b2[oc]), -128), 127) * 128 + 64;
    }

    // ---- stage 1: float4 load + quantize + pack 4 ch/word ----
    for (int g = tid; g < TL / 4; g += NT) {
        int p = ts + 4 * g;
        float4 a = *(const float4*)(xb + p);
        float4 b = *(const float4*)(xb + (size_t)L + p);
        float4 c = *(const float4*)(xb + (size_t)2 * L + p);
        float4 d = *(const float4*)(xb + (size_t)3 * L + p);
        int4 w;
        w.x = qpack(a.x, b.x, c.x, d.x);
        w.y = qpack(a.y, b.y, c.y, d.y);
        w.z = qpack(a.z, b.z, c.z, d.z);
        w.w = qpack(a.w, b.w, c.w, d.w);
        *(int4*)(xs + 4 + 4 * g) = w;
    }
    __syncthreads();

    // ---- stage 2: y = satpack((conv1 + 128*b + 64) >> 7), 4 pos/thread ----
    for (int g = tid; g < (TL + 4) / 4; g += NT) {
        int m = 4 * g;
        int4 va = *(const int4*)(xs + m);
        int4 vb = *(const int4*)(xs + m + 4);
        int xv[8] = {va.x, va.y, va.z, va.w, vb.x, vb.y, vb.z, vb.w};
        int lo[4], hi[4];
#pragma unroll
        for (int p = 0; p < 4; p++) {
            int x0 = xv[p + 1], x1 = xv[p + 2], x2 = xv[p + 3];
            int yv[8];
#pragma unroll
            for (int oc = 0; oc < 8; oc++) {
                int acc = __dp4a(x0, w1p[oc][0], bo1[oc]);
                acc     = __dp4a(x1, w1p[oc][1], acc);
                acc     = __dp4a(x2, w1p[oc][2], acc);
                yv[oc]  = acc >> 7;
            }
            lo[p] = pack4sat(yv[0], yv[1], yv[2], yv[3]);
            hi[p] = pack4sat(yv[4], yv[5], yv[6], yv[7]);
            if (edge) {
                int q = ts - 2 + m + p;
                bool valid = (q >= 0) && (q < L);
                lo[p] = valid ? lo[p] : 0;
                hi[p] = valid ? hi[p] : 0;
            }
        }
        *(int4*)(ysL + m) = make_int4(lo[0], lo[1], lo[2], lo[3]);
        *(int4*)(ysH + m) = make_int4(hi[0], hi[1], hi[2], hi[3]);
    }
    __syncthreads();

    // ---- stage 3: z = dequant(clamp((conv2 + 128*b + 64) >> 7)), 4 pos ----
    float* ob = out + (size_t)bb * 2 * L;
    for (int g = tid; g < TL / 4; g += NT) {
        int j = 4 * g;
        int4 la = *(const int4*)(ysL + j);
        int4 lb = *(const int4*)(ysL + j + 4);
        int4 ha = *(const int4*)(ysH + j);
        int4 hb = *(const int4*)(ysH + j + 4);
        int YL[8] = {la.x, la.y, la.z, la.w, lb.x, lb.y, lb.z, lb.w};
        int YH[8] = {ha.x, ha.y, ha.z, ha.w, hb.x, hb.y, hb.z, hb.w};
        float f0[4], f1[4];
#pragma unroll
        for (int p = 0; p < 4; p++) {
            int a0 = __dp4a(YL[p + 1], w2p[0][0][0], bo2[0]);
            a0     = __dp4a(YH[p + 1], w2p[0][0][1], a0);
            a0     = __dp4a(YL[p + 2], w2p[0][1][0], a0);
            a0     = __dp4a(YH[p + 2], w2p[0][1][1], a0);
            a0     = __dp4a(YL[p + 3], w2p[0][2][0], a0);
            a0     = __dp4a(YH[p + 3], w2p[0][2][1], a0);
            int a1 = __dp4a(YL[p + 1], w2p[1][0][0], bo2[1]);
            a1     = __dp4a(YH[p + 1], w2p[1][0][1], a1);
            a1     = __dp4a(YL[p + 2], w2p[1][1][0], a1);
            a1     = __dp4a(YH[p + 2], w2p[1][1][1], a1);
            a1     = __dp4a(YL[p + 3], w2p[1][2][0], a1);
            a1     = __dp4a(YH[p + 3], w2p[1][2][1], a1);
            f0[p] = (float)min(max(a0 >> 7, -128), 127) * 0.0078125f;
            f1[p] = (float)min(max(a1 >> 7, -128), 127) * 0.0078125f;
        }
        *(float4*)(ob + ts + j)             = make_float4(f0[0], f0[1], f0[2], f0[3]);
        *(float4*)(ob + (size_t)L + ts + j) = make_float4(f1[0], f1[1], f1[2], f1[3]);
    }
}

extern "C" void kernel_launch(void* const* d_in, const int* in_sizes, int n_in,
                              void* d_out, int out_size)
{
    const float* x       = (const float*)d_in[0];
    const float* w1      = (const float*)d_in[1];
    const float* b1      = (const float*)d_in[2];
    const float* gamma   = (const float*)d_in[3];
    const float* beta    = (const float*)d_in[4];
    const float* bn_mean = (const float*)d_in[5];
    const float* bn_var  = (const float*)d_in[6];
    const float* w2      = (const float*)d_in[7];
    const float* b2      = (const float*)d_in[8];
    float* out = (float*)d_out;

    const int B = 16;
    const int L = in_sizes[0] / (B * 4);

    const int smem_bytes = ((TL + 8) + 2 * (TL + 4)) * (int)sizeof(int); // 24.6KB

    dim3 grid((L + TL - 1) / TL, B);
    fused_qconv_i8o<<<grid, NT, smem_bytes>>>(
        x, w1, b1, gamma, beta, bn_mean, bn_var, w2, b2, out, L);
}